// round 1
// baseline (speedup 1.0000x reference)
#include <cuda_runtime.h>
#include <cstdio>

#define NN 100000
#define NE 1600000
#define NG 512

// ---- scratch (device globals; no allocation allowed) ----
__device__ int   g_degout[NN];
__device__ int   g_degin[NN];
__device__ float g_rout[NN];
__device__ float g_rin[NN];
__device__ float g_agg1[NN * 128];   // 51.2 MB
__device__ float g_h1[NN * 256];     // 102.4 MB
__device__ float g_h2in[NN * 64];    // 25.6 MB
__device__ float g_agg2[NN * 64];    // 25.6 MB
__device__ float g_gsum[NG * 64];
__device__ int   g_gcnt[NG];

// ---------------------------------------------------------------------------
__global__ void zero_all_kernel() {
    int i = blockIdx.x * blockDim.x + threadIdx.x;
    int stride = gridDim.x * blockDim.x;
    float4 z = make_float4(0.f, 0.f, 0.f, 0.f);
    float4* a1 = (float4*)g_agg1; const int n1 = NN * 128 / 4;
    for (int j = i; j < n1; j += stride) a1[j] = z;
    float4* a2 = (float4*)g_agg2; const int n2 = NN * 64 / 4;
    for (int j = i; j < n2; j += stride) a2[j] = z;
    float4* gs = (float4*)g_gsum; const int n3 = NG * 64 / 4;
    for (int j = i; j < n3; j += stride) gs[j] = z;
    for (int j = i; j < NN; j += stride) { g_degout[j] = 0; g_degin[j] = 0; }
    for (int j = i; j < NG; j += stride) g_gcnt[j] = 0;
}

__global__ void degree_kernel(const int* __restrict__ src, const int* __restrict__ dst) {
    int e = blockIdx.x * blockDim.x + threadIdx.x;
    if (e < NE) {
        atomicAdd(&g_degout[src[e]], 1);
        atomicAdd(&g_degin[dst[e]], 1);
    }
}

__global__ void finalize_deg_kernel() {
    int i = blockIdx.x * blockDim.x + threadIdx.x;
    if (i < NN) {
        g_rout[i] = rsqrtf((float)max(g_degout[i], 1));
        g_rin[i]  = rsqrtf((float)max(g_degin[i], 1));
    }
}

// 32 lanes per edge, each lane moves one float4 of the 128-dim feature.
__global__ void edge1_kernel(const float* __restrict__ x,
                             const int* __restrict__ src, const int* __restrict__ dst) {
    int t = blockIdx.x * blockDim.x + threadIdx.x;
    int e = t >> 5;
    if (e >= NE) return;
    int lane = t & 31;
    int s = src[e], d = dst[e];
    float ro = g_rout[s];
    float4 v = ((const float4*)(x + (size_t)s * 128))[lane];
    v.x *= ro; v.y *= ro; v.z *= ro; v.w *= ro;
    float* p = g_agg1 + (size_t)d * 128 + lane * 4;
    asm volatile("red.global.add.v4.f32 [%0], {%1,%2,%3,%4};"
                 :: "l"(p), "f"(v.x), "f"(v.y), "f"(v.z), "f"(v.w) : "memory");
}

// 16 lanes per edge, 64-dim features.
__global__ void edge2_kernel(const int* __restrict__ src, const int* __restrict__ dst) {
    int t = blockIdx.x * blockDim.x + threadIdx.x;
    int e = t >> 4;
    if (e >= NE) return;
    int sub = t & 15;
    int s = src[e], d = dst[e];
    float4 v = ((const float4*)(g_h2in + (size_t)s * 64))[sub];
    float* p = g_agg2 + (size_t)d * 64 + sub * 4;
    asm volatile("red.global.add.v4.f32 [%0], {%1,%2,%3,%4};"
                 :: "l"(p), "f"(v.x), "f"(v.y), "f"(v.z), "f"(v.w) : "memory");
}

// C[M,N] = act( rowscale[i] * (A[M,K] @ B[K,N]) + bias[j] )
// BM=BN=64, BK=16, 256 threads, 4x4 per thread.
__global__ void gemm_epilogue_kernel(const float* __restrict__ A, const float* __restrict__ B,
                                     float* __restrict__ C, int M, int N, int K,
                                     const float* __restrict__ rowscale,
                                     const float* __restrict__ bias, int relu) {
    __shared__ float As[16][65];
    __shared__ float Bs[16][64];
    int tid = threadIdx.x;
    int tx = tid & 15, ty = tid >> 4;
    int rowBase = blockIdx.y * 64;
    int colBase = blockIdx.x * 64;
    float acc[4][4] = {};

    for (int k0 = 0; k0 < K; k0 += 16) {
        // A tile: 64 rows x 16 K-cols. Each thread one float4 along K.
        int arow = tid >> 2;
        int ak = (tid & 3) * 4;
        float4 av = make_float4(0.f, 0.f, 0.f, 0.f);
        int gr = rowBase + arow;
        if (gr < M) av = *(const float4*)(A + (size_t)gr * K + k0 + ak);
        As[ak + 0][arow] = av.x;
        As[ak + 1][arow] = av.y;
        As[ak + 2][arow] = av.z;
        As[ak + 3][arow] = av.w;
        // B tile: 16 K-rows x 64 cols.
        int brow = tid >> 4;
        int bn = (tid & 15) * 4;
        float4 bv = *(const float4*)(B + (size_t)(k0 + brow) * N + colBase + bn);
        *(float4*)&Bs[brow][bn] = bv;
        __syncthreads();

        #pragma unroll
        for (int k = 0; k < 16; k++) {
            float a0 = As[k][ty * 4 + 0];
            float a1 = As[k][ty * 4 + 1];
            float a2 = As[k][ty * 4 + 2];
            float a3 = As[k][ty * 4 + 3];
            float4 b4 = *(const float4*)&Bs[k][tx * 4];
            float b[4] = {b4.x, b4.y, b4.z, b4.w};
            #pragma unroll
            for (int j = 0; j < 4; j++) {
                acc[0][j] += a0 * b[j];
                acc[1][j] += a1 * b[j];
                acc[2][j] += a2 * b[j];
                acc[3][j] += a3 * b[j];
            }
        }
        __syncthreads();
    }

    #pragma unroll
    for (int i = 0; i < 4; i++) {
        int r = rowBase + ty * 4 + i;
        if (r >= M) continue;
        float rs = rowscale[r];
        #pragma unroll
        for (int j = 0; j < 4; j++) {
            int c = colBase + tx * 4 + j;
            float v = acc[i][j] * rs + (bias ? bias[c] : 0.f);
            if (relu) v = fmaxf(v, 0.f);
            C[(size_t)r * N + c] = v;
        }
    }
}

// per-node: v = relu(agg2*rin + b2), reduce into per-graph sum + count
__global__ void pool_kernel(const int* __restrict__ gid, const float* __restrict__ b2) {
    int t = blockIdx.x * blockDim.x + threadIdx.x;
    int node = t >> 4;
    if (node >= NN) return;
    int sub = t & 15;
    int g = gid[node];
    float ri = g_rin[node];
    float4 v = ((const float4*)(g_agg2 + (size_t)node * 64))[sub];
    float4 bb = ((const float4*)b2)[sub];
    v.x = fmaxf(v.x * ri + bb.x, 0.f);
    v.y = fmaxf(v.y * ri + bb.y, 0.f);
    v.z = fmaxf(v.z * ri + bb.z, 0.f);
    v.w = fmaxf(v.w * ri + bb.w, 0.f);
    float* p = g_gsum + g * 64 + sub * 4;
    asm volatile("red.global.add.v4.f32 [%0], {%1,%2,%3,%4};"
                 :: "l"(p), "f"(v.x), "f"(v.y), "f"(v.z), "f"(v.w) : "memory");
    if (sub == 0) atomicAdd(&g_gcnt[g], 1);
}

__global__ void classifier_kernel(const float* __restrict__ Wc1, const float* __restrict__ bc1,
                                  const float* __restrict__ Wc2, const float* __restrict__ bc2,
                                  const float* __restrict__ Wc3, const float* __restrict__ bc3,
                                  const float* __restrict__ Wc4, const float* __restrict__ bc4,
                                  float* __restrict__ out) {
    int g = blockIdx.x * blockDim.x + threadIdx.x;
    if (g >= NG) return;
    float inv = 1.f / fmaxf((float)g_gcnt[g], 1.f);
    float h[64];
    #pragma unroll
    for (int j = 0; j < 64; j++) h[j] = g_gsum[g * 64 + j] * inv;
    float t1[18];
    for (int j = 0; j < 18; j++) {
        float s = bc1[j];
        for (int k = 0; k < 64; k++) s += h[k] * Wc1[k * 18 + j];
        t1[j] = s;
    }
    float t2[12];
    for (int j = 0; j < 12; j++) {
        float s = bc2[j];
        for (int k = 0; k < 18; k++) s += t1[k] * Wc2[k * 12 + j];
        t2[j] = s;
    }
    float t3[6];
    for (int j = 0; j < 6; j++) {
        float s = bc3[j];
        for (int k = 0; k < 12; k++) s += t2[k] * Wc3[k * 6 + j];
        t3[j] = s;
    }
    for (int j = 0; j < 2; j++) {
        float s = bc4[j];
        for (int k = 0; k < 6; k++) s += t3[k] * Wc4[k * 2 + j];
        out[g * 2 + j] = s;
    }
}

// ---------------------------------------------------------------------------
extern "C" void kernel_launch(void* const* d_in, const int* in_sizes, int n_in,
                              void* d_out, int out_size) {
    const float* x   = (const float*)d_in[0];
    const int*   src = (const int*)d_in[1];
    const int*   dst = (const int*)d_in[2];
    const int*   gid = (const int*)d_in[3];
    const float* W1  = (const float*)d_in[4];
    const float* b1  = (const float*)d_in[5];
    const float* W2  = (const float*)d_in[6];
    const float* b2  = (const float*)d_in[7];
    const float* Wc1 = (const float*)d_in[8];
    const float* bc1 = (const float*)d_in[9];
    const float* Wc2 = (const float*)d_in[10];
    const float* bc2 = (const float*)d_in[11];
    const float* Wc3 = (const float*)d_in[12];
    const float* bc3 = (const float*)d_in[13];
    const float* Wc4 = (const float*)d_in[14];
    const float* bc4 = (const float*)d_in[15];
    float* out = (float*)d_out;

    float *p_agg1, *p_h1, *p_h2in, *p_rin, *p_rout;
    cudaGetSymbolAddress((void**)&p_agg1, g_agg1);
    cudaGetSymbolAddress((void**)&p_h1,   g_h1);
    cudaGetSymbolAddress((void**)&p_h2in, g_h2in);
    cudaGetSymbolAddress((void**)&p_rin,  g_rin);
    cudaGetSymbolAddress((void**)&p_rout, g_rout);

    zero_all_kernel<<<2048, 256>>>();
    degree_kernel<<<(NE + 255) / 256, 256>>>(src, dst);
    finalize_deg_kernel<<<(NN + 255) / 256, 256>>>();

    // layer 1: agg = segsum(x * rout), h1 = relu(rin * (agg @ W1) + b1)
    edge1_kernel<<<(NE * 32 + 255) / 256, 256>>>(x, src, dst);
    dim3 grid1((256 + 63) / 64, (NN + 63) / 64);
    gemm_epilogue_kernel<<<grid1, 256>>>(p_agg1, W1, p_h1, NN, 256, 128, p_rin, b1, 1);

    // layer 2: h2in = rout * (h1 @ W2); agg2 = segsum(h2in); pool applies rin + b2 + relu
    dim3 grid2((64 + 63) / 64, (NN + 63) / 64);
    gemm_epilogue_kernel<<<grid2, 256>>>(p_h1, W2, p_h2in, NN, 64, 256, p_rout, nullptr, 0);
    edge2_kernel<<<(NE * 16 + 255) / 256, 256>>>(src, dst);

    pool_kernel<<<(NN * 16 + 255) / 256, 256>>>(gid, b2);
    classifier_kernel<<<(NG + 255) / 256, 256>>>(Wc1, bc1, Wc2, bc2, Wc3, bc3, Wc4, bc4, out);
}

// round 2
// speedup vs baseline: 1.5032x; 1.5032x over previous
#include <cuda_runtime.h>

#define NN 100000
#define NE 1600000
#define NG 512
#define NB 98   // ceil(NN/1024)

// ---- scratch (device globals; no allocation allowed) ----
__device__ int   g_degout[NN];
__device__ int   g_degin[NN];
__device__ float g_rout[NN];
__device__ float g_rin[NN];
__device__ int   g_rowptr[NN + 1];
__device__ int   g_cur[NN];
__device__ int   g_partial[NB];
__device__ int   g_base[NB];
__device__ int   g_csrc[NE];
__device__ float g_agg1[NN * 128];   // 51.2 MB
__device__ float g_h1[NN * 256];     // 102.4 MB
__device__ float g_h2in[NN * 64];    // 25.6 MB
__device__ float g_gsum[NG * 64];
__device__ int   g_gcnt[NG];

// ---------------------------------------------------------------------------
__global__ void zero_small_kernel() {
    int i = blockIdx.x * blockDim.x + threadIdx.x;
    int stride = gridDim.x * blockDim.x;
    for (int j = i; j < NN; j += stride) { g_degout[j] = 0; g_degin[j] = 0; }
    for (int j = i; j < NG * 64; j += stride) g_gsum[j] = 0.f;
    for (int j = i; j < NG; j += stride) g_gcnt[j] = 0;
}

__global__ void degree_kernel(const int* __restrict__ src, const int* __restrict__ dst) {
    int e = blockIdx.x * blockDim.x + threadIdx.x;
    if (e < NE) {
        atomicAdd(&g_degout[src[e]], 1);
        atomicAdd(&g_degin[dst[e]], 1);
    }
}

__global__ void finalize_deg_kernel() {
    int i = blockIdx.x * blockDim.x + threadIdx.x;
    if (i < NN) {
        g_rout[i] = rsqrtf((float)max(g_degout[i], 1));
        g_rin[i]  = rsqrtf((float)max(g_degin[i], 1));
    }
}

// ---- 3-phase exclusive scan of g_degin -> g_rowptr -------------------------
__global__ void scanA_kernel() {           // 98 blocks x 1024
    __shared__ int sh[1024];
    int idx = blockIdx.x * 1024 + threadIdx.x;
    sh[threadIdx.x] = (idx < NN) ? g_degin[idx] : 0;
    __syncthreads();
    for (int off = 512; off > 0; off >>= 1) {
        if (threadIdx.x < off) sh[threadIdx.x] += sh[threadIdx.x + off];
        __syncthreads();
    }
    if (threadIdx.x == 0) g_partial[blockIdx.x] = sh[0];
}

__global__ void scanB_kernel() {           // 1 block x 128
    __shared__ int sh[128];
    int t = threadIdx.x;
    sh[t] = (t < NB) ? g_partial[t] : 0;
    __syncthreads();
    if (t == 0) {
        int run = 0;
        for (int b = 0; b < NB; b++) { int v = sh[b]; sh[b] = run; run += v; }
        g_rowptr[NN] = run;
    }
    __syncthreads();
    if (t < NB) g_base[t] = sh[t];
}

__global__ void scanC_kernel() {           // 98 blocks x 1024
    __shared__ int sh[1024];
    int tid = threadIdx.x;
    int idx = blockIdx.x * 1024 + tid;
    int v = (idx < NN) ? g_degin[idx] : 0;
    sh[tid] = v;
    __syncthreads();
    for (int off = 1; off < 1024; off <<= 1) {
        int t2 = 0;
        if (tid >= off) t2 = sh[tid - off];
        __syncthreads();
        sh[tid] += t2;
        __syncthreads();
    }
    if (idx < NN) {
        int excl = sh[tid] - v + g_base[blockIdx.x];
        g_rowptr[idx] = excl;
        g_cur[idx] = excl;
    }
}

__global__ void scatter_kernel(const int* __restrict__ src, const int* __restrict__ dst) {
    int e = blockIdx.x * blockDim.x + threadIdx.x;
    if (e < NE) {
        int pos = atomicAdd(&g_cur[dst[e]], 1);
        g_csrc[pos] = src[e];
    }
}

// ---- layer-1 aggregation: warp per dst node, gather + register accumulate --
__global__ void agg1_kernel(const float* __restrict__ x) {
    int node = (blockIdx.x * blockDim.x + threadIdx.x) >> 5;
    if (node >= NN) return;
    int lane = threadIdx.x & 31;
    int beg = g_rowptr[node], end = g_rowptr[node + 1];
    float4 acc = make_float4(0.f, 0.f, 0.f, 0.f);
    int j = beg;
    for (; j + 1 < end; j += 2) {
        int s0 = g_csrc[j], s1 = g_csrc[j + 1];
        float r0 = g_rout[s0], r1 = g_rout[s1];
        float4 v0 = ((const float4*)(x + (size_t)s0 * 128))[lane];
        float4 v1 = ((const float4*)(x + (size_t)s1 * 128))[lane];
        acc.x += r0 * v0.x + r1 * v1.x;
        acc.y += r0 * v0.y + r1 * v1.y;
        acc.z += r0 * v0.z + r1 * v1.z;
        acc.w += r0 * v0.w + r1 * v1.w;
    }
    if (j < end) {
        int s = g_csrc[j];
        float r = g_rout[s];
        float4 v = ((const float4*)(x + (size_t)s * 128))[lane];
        acc.x += r * v.x; acc.y += r * v.y; acc.z += r * v.z; acc.w += r * v.w;
    }
    ((float4*)(g_agg1 + (size_t)node * 128))[lane] = acc;
}

// ---- GEMM: C = act( rowscale[i]*(A@B) + bias[j] ), BM=128 BN=64 BK=16 ------
__global__ void gemm_epilogue_kernel(const float* __restrict__ A, const float* __restrict__ B,
                                     float* __restrict__ C, int M, int N, int K,
                                     const float* __restrict__ rowscale,
                                     const float* __restrict__ bias, int relu) {
    __shared__ float As[16][132];
    __shared__ float Bs[16][64];
    int tid = threadIdx.x;
    int rowBase = blockIdx.y * 128;
    int colBase = blockIdx.x * 64;
    int tx = tid & 15, ty = tid >> 4;
    float acc[8][4] = {};

    for (int k0 = 0; k0 < K; k0 += 16) {
        int arow = tid >> 1;
        int ak = (tid & 1) * 8;
        int gr = rowBase + arow;
        float4 av0 = make_float4(0.f, 0.f, 0.f, 0.f), av1 = av0;
        if (gr < M) {
            av0 = *(const float4*)(A + (size_t)gr * K + k0 + ak);
            av1 = *(const float4*)(A + (size_t)gr * K + k0 + ak + 4);
        }
        As[ak + 0][arow] = av0.x; As[ak + 1][arow] = av0.y;
        As[ak + 2][arow] = av0.z; As[ak + 3][arow] = av0.w;
        As[ak + 4][arow] = av1.x; As[ak + 5][arow] = av1.y;
        As[ak + 6][arow] = av1.z; As[ak + 7][arow] = av1.w;
        int brow = tid >> 4, bn = (tid & 15) * 4;
        *(float4*)&Bs[brow][bn] = *(const float4*)(B + (size_t)(k0 + brow) * N + colBase + bn);
        __syncthreads();

        #pragma unroll
        for (int k = 0; k < 16; k++) {
            float4 a03 = *(const float4*)&As[k][ty * 8];
            float4 a47 = *(const float4*)&As[k][ty * 8 + 4];
            float4 b4  = *(const float4*)&Bs[k][tx * 4];
            float a[8] = {a03.x, a03.y, a03.z, a03.w, a47.x, a47.y, a47.z, a47.w};
            float b[4] = {b4.x, b4.y, b4.z, b4.w};
            #pragma unroll
            for (int i = 0; i < 8; i++)
                #pragma unroll
                for (int jj = 0; jj < 4; jj++)
                    acc[i][jj] += a[i] * b[jj];
        }
        __syncthreads();
    }

    #pragma unroll
    for (int i = 0; i < 8; i++) {
        int r = rowBase + ty * 8 + i;
        if (r >= M) continue;
        float rs = rowscale[r];
        #pragma unroll
        for (int jj = 0; jj < 4; jj++) {
            int c = colBase + tx * 4 + jj;
            float v = acc[i][jj] * rs + (bias ? bias[c] : 0.f);
            if (relu) v = fmaxf(v, 0.f);
            C[(size_t)r * N + c] = v;
        }
    }
}

// ---- layer-2 aggregation fused with mean-pool reduction --------------------
// warp per node (float2 per lane over 64 dims), then block pre-reduction into
// per-graph sums (graph_ids are sorted -> adjacent nodes share graphs).
__global__ void agg2_pool_kernel(const int* __restrict__ gid, const float* __restrict__ b2) {
    __shared__ float sv[8][64];
    __shared__ int sg[8];
    int wid = threadIdx.x >> 5, lane = threadIdx.x & 31;
    int node = blockIdx.x * 8 + wid;
    float2 acc = make_float2(0.f, 0.f);
    int gv = -1;
    if (node < NN) {
        int beg = g_rowptr[node], end = g_rowptr[node + 1];
        int j = beg;
        for (; j + 1 < end; j += 2) {
            int s0 = g_csrc[j], s1 = g_csrc[j + 1];
            float2 v0 = ((const float2*)(g_h2in + (size_t)s0 * 64))[lane];
            float2 v1 = ((const float2*)(g_h2in + (size_t)s1 * 64))[lane];
            acc.x += v0.x + v1.x;
            acc.y += v0.y + v1.y;
        }
        if (j < end) {
            int s = g_csrc[j];
            float2 v = ((const float2*)(g_h2in + (size_t)s * 64))[lane];
            acc.x += v.x; acc.y += v.y;
        }
        float ri = g_rin[node];
        float2 bb = ((const float2*)b2)[lane];
        acc.x = fmaxf(acc.x * ri + bb.x, 0.f);
        acc.y = fmaxf(acc.y * ri + bb.y, 0.f);
        gv = gid[node];
    }
    sv[wid][lane * 2]     = acc.x;
    sv[wid][lane * 2 + 1] = acc.y;
    if (lane == 0) sg[wid] = gv;
    __syncthreads();

    if (wid == 0) {
        int c0 = lane * 2;
        float a0 = 0.f, a1 = 0.f;
        int cnt = 0;
        int cur = sg[0];
        #pragma unroll
        for (int w = 0; w < 8; w++) {
            int gw = sg[w];
            if (gw != cur) {
                if (cur >= 0) {
                    atomicAdd(&g_gsum[cur * 64 + c0], a0);
                    atomicAdd(&g_gsum[cur * 64 + c0 + 1], a1);
                    if (lane == 0) atomicAdd(&g_gcnt[cur], cnt);
                }
                a0 = 0.f; a1 = 0.f; cnt = 0; cur = gw;
            }
            if (gw >= 0) { a0 += sv[w][c0]; a1 += sv[w][c0 + 1]; cnt++; }
        }
        if (cur >= 0) {
            atomicAdd(&g_gsum[cur * 64 + c0], a0);
            atomicAdd(&g_gsum[cur * 64 + c0 + 1], a1);
            if (lane == 0) atomicAdd(&g_gcnt[cur], cnt);
        }
    }
}

__global__ void classifier_kernel(const float* __restrict__ Wc1, const float* __restrict__ bc1,
                                  const float* __restrict__ Wc2, const float* __restrict__ bc2,
                                  const float* __restrict__ Wc3, const float* __restrict__ bc3,
                                  const float* __restrict__ Wc4, const float* __restrict__ bc4,
                                  float* __restrict__ out) {
    int g = blockIdx.x * blockDim.x + threadIdx.x;
    if (g >= NG) return;
    float inv = 1.f / fmaxf((float)g_gcnt[g], 1.f);
    float h[64];
    #pragma unroll
    for (int j = 0; j < 64; j++) h[j] = g_gsum[g * 64 + j] * inv;
    float t1[18];
    for (int j = 0; j < 18; j++) {
        float s = bc1[j];
        for (int k = 0; k < 64; k++) s += h[k] * Wc1[k * 18 + j];
        t1[j] = s;
    }
    float t2[12];
    for (int j = 0; j < 12; j++) {
        float s = bc2[j];
        for (int k = 0; k < 18; k++) s += t1[k] * Wc2[k * 12 + j];
        t2[j] = s;
    }
    float t3[6];
    for (int j = 0; j < 6; j++) {
        float s = bc3[j];
        for (int k = 0; k < 12; k++) s += t2[k] * Wc3[k * 6 + j];
        t3[j] = s;
    }
    for (int j = 0; j < 2; j++) {
        float s = bc4[j];
        for (int k = 0; k < 6; k++) s += t3[k] * Wc4[k * 2 + j];
        out[g * 2 + j] = s;
    }
}

// ---------------------------------------------------------------------------
extern "C" void kernel_launch(void* const* d_in, const int* in_sizes, int n_in,
                              void* d_out, int out_size) {
    const float* x   = (const float*)d_in[0];
    const int*   src = (const int*)d_in[1];
    const int*   dst = (const int*)d_in[2];
    const int*   gid = (const int*)d_in[3];
    const float* W1  = (const float*)d_in[4];
    const float* b1  = (const float*)d_in[5];
    const float* W2  = (const float*)d_in[6];
    const float* b2  = (const float*)d_in[7];
    const float* Wc1 = (const float*)d_in[8];
    const float* bc1 = (const float*)d_in[9];
    const float* Wc2 = (const float*)d_in[10];
    const float* bc2 = (const float*)d_in[11];
    const float* Wc3 = (const float*)d_in[12];
    const float* bc3 = (const float*)d_in[13];
    const float* Wc4 = (const float*)d_in[14];
    const float* bc4 = (const float*)d_in[15];
    float* out = (float*)d_out;

    float *p_agg1, *p_h1, *p_h2in, *p_rin, *p_rout;
    cudaGetSymbolAddress((void**)&p_agg1, g_agg1);
    cudaGetSymbolAddress((void**)&p_h1,   g_h1);
    cudaGetSymbolAddress((void**)&p_h2in, g_h2in);
    cudaGetSymbolAddress((void**)&p_rin,  g_rin);
    cudaGetSymbolAddress((void**)&p_rout, g_rout);

    zero_small_kernel<<<256, 256>>>();
    degree_kernel<<<(NE + 255) / 256, 256>>>(src, dst);
    finalize_deg_kernel<<<(NN + 255) / 256, 256>>>();

    // CSR build (dst-major)
    scanA_kernel<<<NB, 1024>>>();
    scanB_kernel<<<1, 128>>>();
    scanC_kernel<<<NB, 1024>>>();
    scatter_kernel<<<(NE + 255) / 256, 256>>>(src, dst);

    // layer 1: agg1 = segsum(x * rout); h1 = relu(rin * (agg1 @ W1) + b1)
    agg1_kernel<<<(NN * 32 + 255) / 256, 256>>>(x);
    dim3 grid1(256 / 64, (NN + 127) / 128);
    gemm_epilogue_kernel<<<grid1, 256>>>(p_agg1, W1, p_h1, NN, 256, 128, p_rin, b1, 1);

    // layer 2: h2in = rout * (h1 @ W2); fused gather + pool
    dim3 grid2(1, (NN + 127) / 128);
    gemm_epilogue_kernel<<<grid2, 256>>>(p_h1, W2, p_h2in, NN, 64, 256, p_rout, nullptr, 0);
    agg2_pool_kernel<<<(NN + 7) / 8, 256>>>(gid, b2);

    classifier_kernel<<<(NG + 255) / 256, 256>>>(Wc1, bc1, Wc2, bc2, Wc3, bc3, Wc4, bc4, out);
}